// round 14
// baseline (speedup 1.0000x reference)
#include <cuda_runtime.h>
#include <cuda_fp16.h>
#include <cstdint>

// Problem dims
#define NROWS 16384
#define UDIM  4096
#define KDIM  1024

// GEMM tiling (fp16: 32 elements per 64-byte k-tile row, SW64 swizzle)
#define BM 128
#define BN 128
#define K_TILES 32                // 1024 / 32
#define STAGES 4

#define TILE_BYTES 8192                        // one 128-row x 64B tile
#define STAGE_BYTES (2 * TILE_BYTES)           // A + B = 16 KB
#define SMEM_DATA 1024
#define SMEM_TOTAL (SMEM_DATA + STAGES * STAGE_BYTES)   // 66560 -> 3 CTAs/SM

// ------------------- scratch (pre-swizzled, tiled fp16 operands + norms) -------------------
__device__ __align__(256) __half g_A[(size_t)NROWS * KDIM];  // 32 MB
__device__ __align__(256) __half g_B[(size_t)UDIM  * KDIM];  // 8 MB
__device__ float g_xsq[NROWS];
__device__ float g_wsq[UDIM];

// ------------------- PTX helpers -------------------
#define MBAR_INIT(addr, cnt) \
    asm volatile("mbarrier.init.shared.b64 [%0], %1;" :: "r"(addr), "r"((uint32_t)(cnt)) : "memory")

#define MBAR_EXPECT_TX(addr, bytes) \
    asm volatile("mbarrier.arrive.expect_tx.shared.b64 _, [%0], %1;" \
                 :: "r"(addr), "r"((uint32_t)(bytes)) : "memory")

#define MBAR_ARRIVE(addr) \
    asm volatile("mbarrier.arrive.shared.b64 _, [%0];" :: "r"(addr) : "memory")

#define MBAR_WAIT(addr, parity) do {                                                   \
    uint32_t _mb = (addr); uint32_t _ph = (parity); uint32_t _done;                    \
    asm volatile("{\n\t.reg .pred p;\n\t"                                              \
        "mbarrier.try_wait.parity.acquire.cta.shared::cta.b64 p, [%1], %2;\n\t"        \
        "selp.b32 %0, 1, 0, p;\n\t}"                                                   \
        : "=r"(_done) : "r"(_mb), "r"(_ph) : "memory");                                \
    if (!_done) {                                                                      \
        asm volatile("{\n\t.reg .pred P1;\n\t"                                         \
            "WL%=:\n\t"                                                                \
            "mbarrier.try_wait.parity.acquire.cta.shared::cta.b64 P1, [%0], %1, 0x989680;\n\t" \
            "@P1 bra.uni WD%=;\n\t"                                                    \
            "bra.uni WL%=;\n\t"                                                        \
            "WD%=:\n\t}"                                                               \
            :: "r"(_mb), "r"(_ph) : "memory");                                         \
    }                                                                                  \
} while (0)

__device__ __forceinline__ void bulk_g2s(uint32_t dst, const void* src, uint32_t bytes, uint32_t mbar) {
    asm volatile("cp.async.bulk.shared::cta.global.mbarrier::complete_tx::bytes [%0], [%1], %2, [%3];"
                 :: "r"(dst), "l"(src), "r"(bytes), "r"(mbar) : "memory");
}

__device__ __forceinline__ void ldsm4(uint32_t& r0, uint32_t& r1, uint32_t& r2, uint32_t& r3,
                                      uint32_t addr) {
    asm volatile("ldmatrix.sync.aligned.m8n8.x4.shared.b16 {%0,%1,%2,%3}, [%4];"
                 : "=r"(r0), "=r"(r1), "=r"(r2), "=r"(r3) : "r"(addr));
}

// fp16 MMA with fp16 accumulation: 2 acc regs (4 halves)
__device__ __forceinline__ void mma_f16acc(uint32_t* c, const uint32_t* a, const uint32_t* b) {
    asm volatile(
        "mma.sync.aligned.m16n8k16.row.col.f16.f16.f16.f16 "
        "{%0,%1}, {%2,%3,%4,%5}, {%6,%7}, {%0,%1};"
        : "+r"(c[0]), "+r"(c[1])
        : "r"(a[0]), "r"(a[1]), "r"(a[2]), "r"(a[3]), "r"(b[0]), "r"(b[1]));
}

// ------------------- prepass: fp32 -> fp16, pre-tiled + SW64-swizzled, fused row norms -------------------
// Tile (rt, kt) is a contiguous 8 KB block at ((rt*K_TILES + kt) * 8192); within a tile,
// logical fp16 (r, c) c in [0,32) lives at swz(r*64 + c*2), swz(off) = off ^ ((off>>3)&0x30).
// Warp-per-row: 8 warps/block, 8 float4 loads/lane, warp-shuffle reduce only.
__global__ void __launch_bounds__(256) convert_kernel(const float* __restrict__ x,
                                                      const float* __restrict__ w) {
    int wid = threadIdx.x >> 5, lane = threadIdx.x & 31;
    int row = blockIdx.x * 8 + wid;
    const float* src;
    __half* dst;
    float* sq;
    if (row < NROWS) { src = x; dst = g_A; sq = g_xsq; }
    else { row -= NROWS; src = w; dst = g_B; sq = g_wsq; }

    int rt = row >> 7, r = row & 127;
    const float4* srow = reinterpret_cast<const float4*>(src + (size_t)row * KDIM);
    char* tbase0 = reinterpret_cast<char*>(dst) + (size_t)(rt * K_TILES) * TILE_BYTES;

    // per-lane in-tile offset: c = (lane&7)*4 elements, kt advances by (lane>>3) per iter group
    int ktl = lane >> 3;                       // 0..3
    uint32_t off = (uint32_t)(r * 64 + (lane & 7) * 8);
    uint32_t swz = off ^ ((off >> 3) & 0x30);

    float s = 0.f;
    #pragma unroll
    for (int it = 0; it < 8; it++) {
        float4 v = srow[it * 32 + lane];
        s += v.x * v.x + v.y * v.y + v.z * v.z + v.w * v.w;

        int kt = it * 4 + ktl;
        __half2 lo = __floats2half2_rn(v.x, v.y);
        __half2 hi = __floats2half2_rn(v.z, v.w);
        uint2 packed;
        packed.x = *reinterpret_cast<uint32_t*>(&lo);
        packed.y = *reinterpret_cast<uint32_t*>(&hi);
        *reinterpret_cast<uint2*>(tbase0 + (size_t)kt * TILE_BYTES + swz) = packed;
    }

    #pragma unroll
    for (int o = 16; o > 0; o >>= 1) s += __shfl_xor_sync(0xffffffffu, s, o);
    if (lane == 0) sq[row] = s;
}

// ------------------- GEMM: out[m,u] = xsq[m] + wsq[u] - 2 * sum_k A[m,k] B[u,k] -------------------
// 128 threads, 3 CTAs/SM, 4-stage pipeline (16 KB stages): warp grid 2(M) x 2(N),
// warp tile 64x64. mma.sync m16n8k16 f16acc; elect-one arrives; frag double-buffer.
__global__ void __launch_bounds__(128, 3) gemm_kernel(float* __restrict__ out) {
    extern __shared__ __align__(1024) char smem[];
    uint32_t sb = (uint32_t)__cvta_generic_to_shared(smem);
    uint32_t sdata = sb + SMEM_DATA;

    int tid = threadIdx.x;
    int wid = tid >> 5, lane = tid & 31;
    int wm = wid & 1;        // 0..1 -> M offset wm*64
    int wn = wid >> 1;       // 0..1 -> N offset wn*64
    int bid = blockIdx.x;
    int rt = bid & 127;      // A row-tile 0..127
    int ct = bid >> 7;       // B row-tile 0..31

    uint32_t full0  = sb;                 // STAGES barriers, 8B each
    uint32_t empty0 = sb + STAGES * 8;

    if (tid == 0) {
        #pragma unroll
        for (int s = 0; s < STAGES; s++) {
            MBAR_INIT(full0  + s * 8, 1);
            MBAR_INIT(empty0 + s * 8, 4);   // one arrive per warp
        }
    }
    __syncthreads();

    const char* gA = (const char*)g_A + (size_t)rt * K_TILES * TILE_BYTES;
    const char* gB = (const char*)g_B + (size_t)ct * K_TILES * TILE_BYTES;

    // prologue: fill stages 0..STAGES-2
    if (tid == 0) {
        #pragma unroll
        for (int p = 0; p < STAGES - 1; p++) {
            uint32_t st = sdata + p * STAGE_BYTES;
            MBAR_EXPECT_TX(full0 + p * 8, STAGE_BYTES);
            bulk_g2s(st,              gA + p * TILE_BYTES, TILE_BYTES, full0 + p * 8);
            bulk_g2s(st + TILE_BYTES, gB + p * TILE_BYTES, TILE_BYTES, full0 + p * 8);
        }
    }

    // per-lane ldmatrix addressing (SW64: xor bits 4-5 with (row&6)>>1)
    int lr = lane & 15;                          // row within 16-row fragment
    uint32_t lh = (uint32_t)((lane >> 4) << 4);  // 0 or 16 (16B half of a k16 chunk)
    uint32_t rxor = (uint32_t)(((lr >> 1) & 3) << 4);
    uint32_t arow0 = (uint32_t)((wm * 64 + lr) * 64);
    uint32_t brow0 = (uint32_t)((wn * 64 + lr) * 64);

    uint32_t acc[4][8][2] = {};   // f16x2 accumulators
    uint32_t a[2][4][4];          // [buf][frag i][reg]
    uint32_t b[2][8][2];          // [buf][frag j][reg]

    int s = 0, phF = 0;          // stage cursor + full parity
    #pragma unroll 1
    for (int kt = 0; kt < K_TILES; kt++) {
        // producer first: deep pipeline, issue load for kt+STAGES-1 before full-wait
        if (tid == 0) {
            int ktn = kt + STAGES - 1;
            if (ktn < K_TILES) {
                int sn = ktn & (STAGES - 1);
                int in = ktn >> 2;               // reuse index (STAGES = 4)
                MBAR_WAIT(empty0 + sn * 8, (in & 1) ^ 1);
                uint32_t st = sdata + sn * STAGE_BYTES;
                MBAR_EXPECT_TX(full0 + sn * 8, STAGE_BYTES);
                bulk_g2s(st,              gA + ktn * TILE_BYTES, TILE_BYTES, full0 + sn * 8);
                bulk_g2s(st + TILE_BYTES, gB + ktn * TILE_BYTES, TILE_BYTES, full0 + sn * 8);
            }
        }

        MBAR_WAIT(full0 + s * 8, phF);

        uint32_t abase = sdata + (uint32_t)s * STAGE_BYTES + arow0;
        uint32_t bbase = sdata + (uint32_t)s * STAGE_BYTES + TILE_BYTES + brow0;

        // prime buffer 0 with ks=0 fragments
        {
            uint32_t col = lh ^ rxor;
            #pragma unroll
            for (int i = 0; i < 4; i++)
                ldsm4(a[0][i][0], a[0][i][1], a[0][i][2], a[0][i][3],
                      abase + (uint32_t)(i * 1024) + col);
            #pragma unroll
            for (int q = 0; q < 4; q++) {
                uint32_t r0, r1, r2, r3;
                ldsm4(r0, r1, r2, r3, bbase + (uint32_t)(q * 1024) + col);
                b[0][2 * q][0] = r0; b[0][2 * q + 1][0] = r1;
                b[0][2 * q][1] = r2; b[0][2 * q + 1][1] = r3;
            }
        }

        #pragma unroll
        for (int ks = 0; ks < 2; ks++) {      // 2 x k16 per 64-byte tile
            int cur = ks & 1;
            if (ks < 1) {
                uint32_t col = ((uint32_t)32 + lh) ^ rxor;
                #pragma unroll
                for (int i = 0; i < 4; i++)
                    ldsm4(a[1][i][0], a[1][i][1], a[1][i][2], a[1][i][3],
                          abase + (uint32_t)(i * 1024) + col);
                #pragma unroll
                for (int q = 0; q < 4; q++) {
                    uint32_t r0, r1, r2, r3;
                    ldsm4(r0, r1, r2, r3, bbase + (uint32_t)(q * 1024) + col);
                    b[1][2 * q][0] = r0; b[1][2 * q + 1][0] = r1;
                    b[1][2 * q][1] = r2; b[1][2 * q + 1][1] = r3;
                }
            }
            #pragma unroll
            for (int i = 0; i < 4; i++)
                #pragma unroll
                for (int j = 0; j < 8; j++)
                    mma_f16acc(acc[i][j], a[cur][i], b[cur][j]);
        }

        if (lane == 0) MBAR_ARRIVE(empty0 + s * 8);
        s++;
        if (s == STAGES) { s = 0; phF ^= 1; }
    }

    // ---------------- epilogue: out = xsq + wsq - 2*acc ----------------
    // f16 acc layout: acc[i][j][0] = halves (row r, cols c2, c2+1); acc[i][j][1] = row r+8.
    int m0 = rt * BM + wm * 64;
    int n0 = ct * BN + wn * 64;
    int r = lane >> 2;
    int c2 = (lane & 3) * 2;

    #pragma unroll
    for (int i = 0; i < 4; i++) {
        int mA = m0 + i * 16 + r;
        float xs0 = __ldg(&g_xsq[mA]);
        float xs1 = __ldg(&g_xsq[mA + 8]);
        float* row0 = out + (size_t)mA * UDIM + n0;
        float* row1 = row0 + (size_t)8 * UDIM;
        #pragma unroll
        for (int j = 0; j < 8; j++) {
            float w0 = __ldg(&g_wsq[n0 + j * 8 + c2]);
            float w1 = __ldg(&g_wsq[n0 + j * 8 + c2 + 1]);
            float2 p0 = __half22float2(*reinterpret_cast<__half2*>(&acc[i][j][0]));
            float2 p1 = __half22float2(*reinterpret_cast<__half2*>(&acc[i][j][1]));
            float2 v0, v1;
            v0.x = xs0 + w0 - 2.0f * p0.x;
            v0.y = xs0 + w1 - 2.0f * p0.y;
            v1.x = xs1 + w0 - 2.0f * p1.x;
            v1.y = xs1 + w1 - 2.0f * p1.y;
            *reinterpret_cast<float2*>(row0 + j * 8 + c2) = v0;
            *reinterpret_cast<float2*>(row1 + j * 8 + c2) = v1;
        }
    }
}

// ------------------- launch -------------------
extern "C" void kernel_launch(void* const* d_in, const int* in_sizes, int n_in,
                              void* d_out, int out_size) {
    (void)in_sizes; (void)n_in; (void)out_size;
    const float* x = (const float*)d_in[0];   // [16384, 1024]
    const float* w = (const float*)d_in[1];   // [4096, 1024]
    float* out = (float*)d_out;               // [16384, 4096]

    cudaFuncSetAttribute(gemm_kernel, cudaFuncAttributeMaxDynamicSharedMemorySize, SMEM_TOTAL);

    convert_kernel<<<(NROWS + UDIM) / 8, 256>>>(x, w);
    gemm_kernel<<<(NROWS / BM) * (UDIM / BN), 128, SMEM_TOTAL>>>(out);
}

// round 15
// speedup vs baseline: 1.0791x; 1.0791x over previous
#include <cuda_runtime.h>
#include <cuda_fp16.h>
#include <cstdint>

// Problem dims
#define NROWS 16384
#define UDIM  4096
#define KDIM  1024

// GEMM tiling (fp16: 64 elements per 128-byte k-tile row)
#define BM 128
#define BN 128
#define K_TILES 16                // 1024 / 64
#define STAGES 2

#define TILE_BYTES 16384                       // one 128-row x 128B tile
#define STAGE_BYTES (2 * TILE_BYTES)           // A + B = 32 KB
#define SMEM_DATA 1024
#define SMEM_TOTAL (SMEM_DATA + STAGES * STAGE_BYTES)   // 66560 -> 3 CTAs/SM

// ------------------- scratch (pre-swizzled, tiled fp16 operands + norms) -------------------
__device__ __align__(256) __half g_A[(size_t)NROWS * KDIM];  // 32 MB
__device__ __align__(256) __half g_B[(size_t)UDIM  * KDIM];  // 8 MB
__device__ float g_xsq[NROWS];
__device__ float g_wsq[UDIM];

// ------------------- PTX helpers -------------------
#define MBAR_INIT(addr, cnt) \
    asm volatile("mbarrier.init.shared.b64 [%0], %1;" :: "r"(addr), "r"((uint32_t)(cnt)) : "memory")

#define MBAR_EXPECT_TX(addr, bytes) \
    asm volatile("mbarrier.arrive.expect_tx.shared.b64 _, [%0], %1;" \
                 :: "r"(addr), "r"((uint32_t)(bytes)) : "memory")

#define MBAR_ARRIVE(addr) \
    asm volatile("mbarrier.arrive.shared.b64 _, [%0];" :: "r"(addr) : "memory")

#define MBAR_WAIT(addr, parity) do {                                                   \
    uint32_t _mb = (addr); uint32_t _ph = (parity); uint32_t _done;                    \
    asm volatile("{\n\t.reg .pred p;\n\t"                                              \
        "mbarrier.try_wait.parity.acquire.cta.shared::cta.b64 p, [%1], %2;\n\t"        \
        "selp.b32 %0, 1, 0, p;\n\t}"                                                   \
        : "=r"(_done) : "r"(_mb), "r"(_ph) : "memory");                                \
    if (!_done) {                                                                      \
        asm volatile("{\n\t.reg .pred P1;\n\t"                                         \
            "WL%=:\n\t"                                                                \
            "mbarrier.try_wait.parity.acquire.cta.shared::cta.b64 P1, [%0], %1, 0x989680;\n\t" \
            "@P1 bra.uni WD%=;\n\t"                                                    \
            "bra.uni WL%=;\n\t"                                                        \
            "WD%=:\n\t}"                                                               \
            :: "r"(_mb), "r"(_ph) : "memory");                                         \
    }                                                                                  \
} while (0)

__device__ __forceinline__ void bulk_g2s(uint32_t dst, const void* src, uint32_t bytes, uint32_t mbar) {
    asm volatile("cp.async.bulk.shared::cta.global.mbarrier::complete_tx::bytes [%0], [%1], %2, [%3];"
                 :: "r"(dst), "l"(src), "r"(bytes), "r"(mbar) : "memory");
}

__device__ __forceinline__ void ldsm4(uint32_t& r0, uint32_t& r1, uint32_t& r2, uint32_t& r3,
                                      uint32_t addr) {
    asm volatile("ldmatrix.sync.aligned.m8n8.x4.shared.b16 {%0,%1,%2,%3}, [%4];"
                 : "=r"(r0), "=r"(r1), "=r"(r2), "=r"(r3) : "r"(addr));
}

// fp16 MMA with fp16 accumulation: 2 acc regs (4 halves)
__device__ __forceinline__ void mma_f16acc(uint32_t* c, const uint32_t* a, const uint32_t* b) {
    asm volatile(
        "mma.sync.aligned.m16n8k16.row.col.f16.f16.f16.f16 "
        "{%0,%1}, {%2,%3,%4,%5}, {%6,%7}, {%0,%1};"
        : "+r"(c[0]), "+r"(c[1])
        : "r"(a[0]), "r"(a[1]), "r"(a[2]), "r"(a[3]), "r"(b[0]), "r"(b[1]));
}

// ------------------- prepass: fp32 -> fp16, pre-tiled + SW128-swizzled, fused row norms -------------------
// Tile (rt, kt) is a contiguous 16 KB block at ((rt*K_TILES + kt) * 16384); within a tile,
// logical fp16 (r, c) lives at swz(r*128 + c*2), swz(off) = off ^ ((off>>3)&0x70).
// Warp-per-row: 8 warps/block, 8 float4 loads/lane, warp-shuffle reduce only.
__global__ void __launch_bounds__(256) convert_kernel(const float* __restrict__ x,
                                                      const float* __restrict__ w) {
    int wid = threadIdx.x >> 5, lane = threadIdx.x & 31;
    int row = blockIdx.x * 8 + wid;
    const float* src;
    __half* dst;
    float* sq;
    if (row < NROWS) { src = x; dst = g_A; sq = g_xsq; }
    else { row -= NROWS; src = w; dst = g_B; sq = g_wsq; }

    int rt = row >> 7, r = row & 127;
    const float4* srow = reinterpret_cast<const float4*>(src + (size_t)row * KDIM);
    char* tbase0 = reinterpret_cast<char*>(dst) + (size_t)(rt * K_TILES) * TILE_BYTES;

    float s = 0.f;
    #pragma unroll
    for (int it = 0; it < 8; it++) {
        int idx = it * 128 + lane * 4;           // element index within the row
        float4 v = srow[it * 32 + lane];
        s += v.x * v.x + v.y * v.y + v.z * v.z + v.w * v.w;

        int kt = idx >> 6;
        int c  = idx & 63;
        uint32_t off = (uint32_t)(r * 128 + c * 2);
        uint32_t swz = off ^ ((off >> 3) & 0x70);

        __half2 lo = __floats2half2_rn(v.x, v.y);
        __half2 hi = __floats2half2_rn(v.z, v.w);
        uint2 packed;
        packed.x = *reinterpret_cast<uint32_t*>(&lo);
        packed.y = *reinterpret_cast<uint32_t*>(&hi);
        *reinterpret_cast<uint2*>(tbase0 + (size_t)kt * TILE_BYTES + swz) = packed;
    }

    #pragma unroll
    for (int o = 16; o > 0; o >>= 1) s += __shfl_xor_sync(0xffffffffu, s, o);
    if (lane == 0) sq[row] = s;
}

// ------------------- GEMM: out[m,u] = xsq[m] + wsq[u] - 2 * sum_k A[m,k] B[u,k] -------------------
// 128 threads, 3 CTAs/SM, 2-stage pipeline: warp grid 2(M) x 2(N), warp tile 64x64.
// Cross-tile software pipeline: the full-wait + ks=0 fragment prime for tile kt+1
// happen at ks=3 of tile kt, hidden under kt's mma stream.
__global__ void __launch_bounds__(128, 3) gemm_kernel(float* __restrict__ out) {
    extern __shared__ __align__(1024) char smem[];
    uint32_t sb = (uint32_t)__cvta_generic_to_shared(smem);
    uint32_t sdata = sb + SMEM_DATA;

    int tid = threadIdx.x;
    int wid = tid >> 5, lane = tid & 31;
    int wm = wid & 1;        // 0..1 -> M offset wm*64
    int wn = wid >> 1;       // 0..1 -> N offset wn*64
    int bid = blockIdx.x;
    int rt = bid & 127;      // A row-tile 0..127
    int ct = bid >> 7;       // B row-tile 0..31

    uint32_t full0  = sb;                 // STAGES barriers, 8B each
    uint32_t empty0 = sb + STAGES * 8;

    if (tid == 0) {
        #pragma unroll
        for (int s = 0; s < STAGES; s++) {
            MBAR_INIT(full0  + s * 8, 1);
            MBAR_INIT(empty0 + s * 8, 4);   // one arrive per warp
        }
    }
    __syncthreads();

    const char* gA = (const char*)g_A + (size_t)rt * K_TILES * TILE_BYTES;
    const char* gB = (const char*)g_B + (size_t)ct * K_TILES * TILE_BYTES;

    // prologue: fill stage 0 (kt = 0)
    if (tid == 0) {
        MBAR_EXPECT_TX(full0, STAGE_BYTES);
        bulk_g2s(sdata,              gA, TILE_BYTES, full0);
        bulk_g2s(sdata + TILE_BYTES, gB, TILE_BYTES, full0);
    }

    // per-lane ldmatrix addressing
    int lr = lane & 15;                          // row within 16-row fragment
    uint32_t lh = (uint32_t)((lane >> 4) << 4);  // 0 or 16 (k-half bytes)
    uint32_t rxor = (uint32_t)((lr & 7) << 4);   // SW128 xor (frag bases are mult of 8 rows)
    uint32_t arow0 = (uint32_t)((wm * 64 + lr) * 128);
    uint32_t brow0 = (uint32_t)((wn * 64 + lr) * 128);

    uint32_t acc[4][8][2] = {};   // f16x2 accumulators
    uint32_t a[2][4][4];          // [buf][frag i][reg]
    uint32_t b[2][8][2];          // [buf][frag j][reg]

    // prologue: wait stage 0, prime buffer 0 with kt=0 ks=0 fragments
    MBAR_WAIT(full0, 0);
    {
        uint32_t abase = sdata + arow0;
        uint32_t bbase = sdata + TILE_BYTES + brow0;
        uint32_t col = lh ^ rxor;
        #pragma unroll
        for (int i = 0; i < 4; i++)
            ldsm4(a[0][i][0], a[0][i][1], a[0][i][2], a[0][i][3],
                  abase + (uint32_t)(i * 16 * 128) + col);
        #pragma unroll
        for (int q = 0; q < 4; q++) {
            uint32_t r0, r1, r2, r3;
            ldsm4(r0, r1, r2, r3, bbase + (uint32_t)(q * 16 * 128) + col);
            b[0][2 * q][0] = r0; b[0][2 * q + 1][0] = r1;
            b[0][2 * q][1] = r2; b[0][2 * q + 1][1] = r3;
        }
    }

    #pragma unroll 1
    for (int kt = 0; kt < K_TILES; kt++) {
        int s = kt & 1;

        // producer: issue TMA for kt+1 into the other stage (its consumers
        // finished at kt-1); goes out before any mma of this tile.
        if (tid == 0) {
            int ktn = kt + 1;
            if (ktn < K_TILES) {
                int sn = ktn & 1;
                int in = ktn >> 1;
                MBAR_WAIT(empty0 + sn * 8, (in & 1) ^ 1);
                uint32_t st = sdata + sn * STAGE_BYTES;
                MBAR_EXPECT_TX(full0 + sn * 8, STAGE_BYTES);
                bulk_g2s(st,              gA + ktn * TILE_BYTES, TILE_BYTES, full0 + sn * 8);
                bulk_g2s(st + TILE_BYTES, gB + ktn * TILE_BYTES, TILE_BYTES, full0 + sn * 8);
            }
        }

        uint32_t abase = sdata + (uint32_t)s * STAGE_BYTES + arow0;
        uint32_t bbase = sdata + (uint32_t)s * STAGE_BYTES + TILE_BYTES + brow0;

        #pragma unroll
        for (int ks = 0; ks < 4; ks++) {
            int cur = ks & 1;
            int nxt = cur ^ 1;
            if (ks < 3) {
                // prefetch ks+1 fragments from the current stage
                uint32_t col = ((uint32_t)((ks + 1) * 32) + lh) ^ rxor;
                #pragma unroll
                for (int i = 0; i < 4; i++)
                    ldsm4(a[nxt][i][0], a[nxt][i][1], a[nxt][i][2], a[nxt][i][3],
                          abase + (uint32_t)(i * 16 * 128) + col);
                #pragma unroll
                for (int q = 0; q < 4; q++) {
                    uint32_t r0, r1, r2, r3;
                    ldsm4(r0, r1, r2, r3, bbase + (uint32_t)(q * 16 * 128) + col);
                    b[nxt][2 * q][0] = r0; b[nxt][2 * q + 1][0] = r1;
                    b[nxt][2 * q][1] = r2; b[nxt][2 * q + 1][1] = r3;
                }
            } else if (kt + 1 < K_TILES) {
                // cross-tile: wait for kt+1's stage (TMA issued a full k-tile ago,
                // normally fast-path) and prime its ks=0 fragments, all while this
                // tile's ks=2/3 mmas drain through the tensor pipe.
                int sn = s ^ 1;
                MBAR_WAIT(full0 + sn * 8, ((kt + 1) >> 1) & 1);
                uint32_t abn = sdata + (uint32_t)sn * STAGE_BYTES + arow0;
                uint32_t bbn = sdata + (uint32_t)sn * STAGE_BYTES + TILE_BYTES + brow0;
                uint32_t col = lh ^ rxor;
                #pragma unroll
                for (int i = 0; i < 4; i++)
                    ldsm4(a[nxt][i][0], a[nxt][i][1], a[nxt][i][2], a[nxt][i][3],
                          abn + (uint32_t)(i * 16 * 128) + col);
                #pragma unroll
                for (int q = 0; q < 4; q++) {
                    uint32_t r0, r1, r2, r3;
                    ldsm4(r0, r1, r2, r3, bbn + (uint32_t)(q * 16 * 128) + col);
                    b[nxt][2 * q][0] = r0; b[nxt][2 * q + 1][0] = r1;
                    b[nxt][2 * q][1] = r2; b[nxt][2 * q + 1][1] = r3;
                }
            }
            #pragma unroll
            for (int i = 0; i < 4; i++)
                #pragma unroll
                for (int j = 0; j < 8; j++)
                    mma_f16acc(acc[i][j], a[cur][i], b[cur][j]);
        }

        // all reads of stage s finished at the ks=2 prefetch; release it.
        if (lane == 0) MBAR_ARRIVE(empty0 + s * 8);
    }

    // ---------------- epilogue: out = xsq + wsq - 2*acc ----------------
    // f16 acc layout: acc[i][j][0] = halves (row r, cols c2, c2+1); acc[i][j][1] = row r+8.
    int m0 = rt * BM + wm * 64;
    int n0 = ct * BN + wn * 64;
    int r = lane >> 2;
    int c2 = (lane & 3) * 2;

    #pragma unroll
    for (int i = 0; i < 4; i++) {
        int mA = m0 + i * 16 + r;
        float xs0 = __ldg(&g_xsq[mA]);
        float xs1 = __ldg(&g_xsq[mA + 8]);
        float* row0 = out + (size_t)mA * UDIM + n0;
        float* row1 = row0 + (size_t)8 * UDIM;
        #pragma unroll
        for (int j = 0; j < 8; j++) {
            float w0 = __ldg(&g_wsq[n0 + j * 8 + c2]);
            float w1 = __ldg(&g_wsq[n0 + j * 8 + c2 + 1]);
            float2 p0 = __half22float2(*reinterpret_cast<__half2*>(&acc[i][j][0]));
            float2 p1 = __half22float2(*reinterpret_cast<__half2*>(&acc[i][j][1]));
            float2 v0, v1;
            v0.x = xs0 + w0 - 2.0f * p0.x;
            v0.y = xs0 + w1 - 2.0f * p0.y;
            v1.x = xs1 + w0 - 2.0f * p1.x;
            v1.y = xs1 + w1 - 2.0f * p1.y;
            *reinterpret_cast<float2*>(row0 + j * 8 + c2) = v0;
            *reinterpret_cast<float2*>(row1 + j * 8 + c2) = v1;
        }
    }
}

// ------------------- launch -------------------
extern "C" void kernel_launch(void* const* d_in, const int* in_sizes, int n_in,
                              void* d_out, int out_size) {
    (void)in_sizes; (void)n_in; (void)out_size;
    const float* x = (const float*)d_in[0];   // [16384, 1024]
    const float* w = (const float*)d_in[1];   // [4096, 1024]
    float* out = (float*)d_out;               // [16384, 4096]

    cudaFuncSetAttribute(gemm_kernel, cudaFuncAttributeMaxDynamicSharedMemorySize, SMEM_TOTAL);

    convert_kernel<<<(NROWS + UDIM) / 8, 256>>>(x, w);
    gemm_kernel<<<(NROWS / BM) * (UDIM / BN), 128, SMEM_TOTAL>>>(out);
}

// round 16
// speedup vs baseline: 1.0809x; 1.0016x over previous
#include <cuda_runtime.h>
#include <cuda_fp16.h>
#include <cstdint>

// Problem dims
#define NROWS 16384
#define UDIM  4096
#define KDIM  1024

// GEMM tiling (fp16: 64 elements per 128-byte k-tile row)
#define BM 128
#define BN 128
#define K_TILES 16                // 1024 / 64
#define STAGES 2

#define TILE_BYTES 16384                       // one 128-row x 128B tile
#define STAGE_BYTES (2 * TILE_BYTES)           // A + B = 32 KB
#define SMEM_DATA 1024
#define SMEM_TOTAL (SMEM_DATA + STAGES * STAGE_BYTES)   // 66560 -> 3 CTAs/SM

// ------------------- scratch (pre-swizzled, tiled fp16 operands + norms) -------------------
__device__ __align__(256) __half g_A[(size_t)NROWS * KDIM];  // 32 MB
__device__ __align__(256) __half g_B[(size_t)UDIM  * KDIM];  // 8 MB
__device__ float g_xsq[NROWS];
__device__ float g_wsq[UDIM];

// ------------------- PTX helpers -------------------
#define MBAR_INIT(addr, cnt) \
    asm volatile("mbarrier.init.shared.b64 [%0], %1;" :: "r"(addr), "r"((uint32_t)(cnt)) : "memory")

#define MBAR_EXPECT_TX(addr, bytes) \
    asm volatile("mbarrier.arrive.expect_tx.shared.b64 _, [%0], %1;" \
                 :: "r"(addr), "r"((uint32_t)(bytes)) : "memory")

#define MBAR_ARRIVE(addr) \
    asm volatile("mbarrier.arrive.shared.b64 _, [%0];" :: "r"(addr) : "memory")

#define MBAR_WAIT(addr, parity) do {                                                   \
    uint32_t _mb = (addr); uint32_t _ph = (parity); uint32_t _done;                    \
    asm volatile("{\n\t.reg .pred p;\n\t"                                              \
        "mbarrier.try_wait.parity.acquire.cta.shared::cta.b64 p, [%1], %2;\n\t"        \
        "selp.b32 %0, 1, 0, p;\n\t}"                                                   \
        : "=r"(_done) : "r"(_mb), "r"(_ph) : "memory");                                \
    if (!_done) {                                                                      \
        asm volatile("{\n\t.reg .pred P1;\n\t"                                         \
            "WL%=:\n\t"                                                                \
            "mbarrier.try_wait.parity.acquire.cta.shared::cta.b64 P1, [%0], %1, 0x989680;\n\t" \
            "@P1 bra.uni WD%=;\n\t"                                                    \
            "bra.uni WL%=;\n\t"                                                        \
            "WD%=:\n\t}"                                                               \
            :: "r"(_mb), "r"(_ph) : "memory");                                         \
    }                                                                                  \
} while (0)

__device__ __forceinline__ void bulk_g2s(uint32_t dst, const void* src, uint32_t bytes, uint32_t mbar) {
    asm volatile("cp.async.bulk.shared::cta.global.mbarrier::complete_tx::bytes [%0], [%1], %2, [%3];"
                 :: "r"(dst), "l"(src), "r"(bytes), "r"(mbar) : "memory");
}

__device__ __forceinline__ void ldsm4(uint32_t& r0, uint32_t& r1, uint32_t& r2, uint32_t& r3,
                                      uint32_t addr) {
    asm volatile("ldmatrix.sync.aligned.m8n8.x4.shared.b16 {%0,%1,%2,%3}, [%4];"
                 : "=r"(r0), "=r"(r1), "=r"(r2), "=r"(r3) : "r"(addr));
}

// fp16 MMA with fp16 accumulation: 2 acc regs (4 halves)
__device__ __forceinline__ void mma_f16acc(uint32_t* c, const uint32_t* a, const uint32_t* b) {
    asm volatile(
        "mma.sync.aligned.m16n8k16.row.col.f16.f16.f16.f16 "
        "{%0,%1}, {%2,%3,%4,%5}, {%6,%7}, {%0,%1};"
        : "+r"(c[0]), "+r"(c[1])
        : "r"(a[0]), "r"(a[1]), "r"(a[2]), "r"(a[3]), "r"(b[0]), "r"(b[1]));
}

// ------------------- prepass: fp32 -> fp16, pre-tiled + SW128-swizzled, fused row norms -------------------
// Tile (rt, kt) is a contiguous 16 KB block at ((rt*K_TILES + kt) * 16384); within a tile,
// logical fp16 (r, c) lives at swz(r*128 + c*2), swz(off) = off ^ ((off>>3)&0x70).
// Warp-per-row: 8 warps/block, 8 float4 loads/lane, warp-shuffle reduce only.
__global__ void __launch_bounds__(256) convert_kernel(const float* __restrict__ x,
                                                      const float* __restrict__ w) {
    int wid = threadIdx.x >> 5, lane = threadIdx.x & 31;
    int row = blockIdx.x * 8 + wid;
    const float* src;
    __half* dst;
    float* sq;
    if (row < NROWS) { src = x; dst = g_A; sq = g_xsq; }
    else { row -= NROWS; src = w; dst = g_B; sq = g_wsq; }

    int rt = row >> 7, r = row & 127;
    const float4* srow = reinterpret_cast<const float4*>(src + (size_t)row * KDIM);
    char* tbase0 = reinterpret_cast<char*>(dst) + (size_t)(rt * K_TILES) * TILE_BYTES;

    float s = 0.f;
    #pragma unroll
    for (int it = 0; it < 8; it++) {
        int idx = it * 128 + lane * 4;           // element index within the row
        float4 v = srow[it * 32 + lane];
        s += v.x * v.x + v.y * v.y + v.z * v.z + v.w * v.w;

        int kt = idx >> 6;
        int c  = idx & 63;
        uint32_t off = (uint32_t)(r * 128 + c * 2);
        uint32_t swz = off ^ ((off >> 3) & 0x70);

        __half2 lo = __floats2half2_rn(v.x, v.y);
        __half2 hi = __floats2half2_rn(v.z, v.w);
        uint2 packed;
        packed.x = *reinterpret_cast<uint32_t*>(&lo);
        packed.y = *reinterpret_cast<uint32_t*>(&hi);
        *reinterpret_cast<uint2*>(tbase0 + (size_t)kt * TILE_BYTES + swz) = packed;
    }

    #pragma unroll
    for (int o = 16; o > 0; o >>= 1) s += __shfl_xor_sync(0xffffffffu, s, o);
    if (lane == 0) sq[row] = s;
}

// ------------------- GEMM: out[m,u] = xsq[m] + wsq[u] - 2 * sum_k A[m,k] B[u,k] -------------------
// 128 threads, 3 CTAs/SM, 2-stage pipeline: warp grid 2(M) x 2(N), warp tile 64x64.
// Cross-tile software pipeline; producer rotates across warps (kt & 3) so TMA-issue
// overhead is spread over all 4 SMSPs; stage released early at the ks=2 prefetch.
__global__ void __launch_bounds__(128, 3) gemm_kernel(float* __restrict__ out) {
    extern __shared__ __align__(1024) char smem[];
    uint32_t sb = (uint32_t)__cvta_generic_to_shared(smem);
    uint32_t sdata = sb + SMEM_DATA;

    int tid = threadIdx.x;
    int wid = tid >> 5, lane = tid & 31;
    int wm = wid & 1;        // 0..1 -> M offset wm*64
    int wn = wid >> 1;       // 0..1 -> N offset wn*64
    int bid = blockIdx.x;
    int rt = bid & 127;      // A row-tile 0..127
    int ct = bid >> 7;       // B row-tile 0..31

    uint32_t full0  = sb;                 // STAGES barriers, 8B each
    uint32_t empty0 = sb + STAGES * 8;

    if (tid == 0) {
        #pragma unroll
        for (int s = 0; s < STAGES; s++) {
            MBAR_INIT(full0  + s * 8, 1);
            MBAR_INIT(empty0 + s * 8, 4);   // one arrive per warp
        }
    }
    __syncthreads();

    const char* gA = (const char*)g_A + (size_t)rt * K_TILES * TILE_BYTES;
    const char* gB = (const char*)g_B + (size_t)ct * K_TILES * TILE_BYTES;

    // prologue: fill stage 0 (kt = 0)
    if (tid == 0) {
        MBAR_EXPECT_TX(full0, STAGE_BYTES);
        bulk_g2s(sdata,              gA, TILE_BYTES, full0);
        bulk_g2s(sdata + TILE_BYTES, gB, TILE_BYTES, full0);
    }

    // per-lane ldmatrix addressing
    int lr = lane & 15;                          // row within 16-row fragment
    uint32_t lh = (uint32_t)((lane >> 4) << 4);  // 0 or 16 (k-half bytes)
    uint32_t rxor = (uint32_t)((lr & 7) << 4);   // SW128 xor (frag bases are mult of 8 rows)
    uint32_t arow0 = (uint32_t)((wm * 64 + lr) * 128);
    uint32_t brow0 = (uint32_t)((wn * 64 + lr) * 128);

    uint32_t acc[4][8][2] = {};   // f16x2 accumulators
    uint32_t a[2][4][4];          // [buf][frag i][reg]
    uint32_t b[2][8][2];          // [buf][frag j][reg]

    // prologue: wait stage 0, prime buffer 0 with kt=0 ks=0 fragments
    MBAR_WAIT(full0, 0);
    {
        uint32_t abase = sdata + arow0;
        uint32_t bbase = sdata + TILE_BYTES + brow0;
        uint32_t col = lh ^ rxor;
        #pragma unroll
        for (int i = 0; i < 4; i++)
            ldsm4(a[0][i][0], a[0][i][1], a[0][i][2], a[0][i][3],
                  abase + (uint32_t)(i * 16 * 128) + col);
        #pragma unroll
        for (int q = 0; q < 4; q++) {
            uint32_t r0, r1, r2, r3;
            ldsm4(r0, r1, r2, r3, bbase + (uint32_t)(q * 16 * 128) + col);
            b[0][2 * q][0] = r0; b[0][2 * q + 1][0] = r1;
            b[0][2 * q][1] = r2; b[0][2 * q + 1][1] = r3;
        }
    }

    #pragma unroll 1
    for (int kt = 0; kt < K_TILES; kt++) {
        int s = kt & 1;

        // producer (rotating warp kt&3, lane 0): issue TMA for kt+1 into the
        // other stage; spreads TMA-issue overhead across all 4 SMSPs.
        if (wid == (kt & 3) && lane == 0) {
            int ktn = kt + 1;
            if (ktn < K_TILES) {
                int sn = ktn & 1;
                int in = ktn >> 1;
                MBAR_WAIT(empty0 + sn * 8, (in & 1) ^ 1);
                uint32_t st = sdata + sn * STAGE_BYTES;
                MBAR_EXPECT_TX(full0 + sn * 8, STAGE_BYTES);
                bulk_g2s(st,              gA + ktn * TILE_BYTES, TILE_BYTES, full0 + sn * 8);
                bulk_g2s(st + TILE_BYTES, gB + ktn * TILE_BYTES, TILE_BYTES, full0 + sn * 8);
            }
        }

        uint32_t abase = sdata + (uint32_t)s * STAGE_BYTES + arow0;
        uint32_t bbase = sdata + (uint32_t)s * STAGE_BYTES + TILE_BYTES + brow0;

        #pragma unroll
        for (int ks = 0; ks < 4; ks++) {
            int cur = ks & 1;
            int nxt = cur ^ 1;
            if (ks < 3) {
                // prefetch ks+1 fragments from the current stage
                uint32_t col = ((uint32_t)((ks + 1) * 32) + lh) ^ rxor;
                #pragma unroll
                for (int i = 0; i < 4; i++)
                    ldsm4(a[nxt][i][0], a[nxt][i][1], a[nxt][i][2], a[nxt][i][3],
                          abase + (uint32_t)(i * 16 * 128) + col);
                #pragma unroll
                for (int q = 0; q < 4; q++) {
                    uint32_t r0, r1, r2, r3;
                    ldsm4(r0, r1, r2, r3, bbase + (uint32_t)(q * 16 * 128) + col);
                    b[nxt][2 * q][0] = r0; b[nxt][2 * q + 1][0] = r1;
                    b[nxt][2 * q][1] = r2; b[nxt][2 * q + 1][1] = r3;
                }
                // last read of stage s is this ks=2 prefetch: release it now so
                // the next tile's producer gets ~750 cyc more TMA lead.
                if (ks == 2 && lane == 0) MBAR_ARRIVE(empty0 + s * 8);
            } else if (kt + 1 < K_TILES) {
                // cross-tile: wait for kt+1's stage (TMA issued a full k-tile ago,
                // normally fast-path) and prime its ks=0 fragments under the drain.
                int sn = s ^ 1;
                MBAR_WAIT(full0 + sn * 8, ((kt + 1) >> 1) & 1);
                uint32_t abn = sdata + (uint32_t)sn * STAGE_BYTES + arow0;
                uint32_t bbn = sdata + (uint32_t)sn * STAGE_BYTES + TILE_BYTES + brow0;
                uint32_t col = lh ^ rxor;
                #pragma unroll
                for (int i = 0; i < 4; i++)
                    ldsm4(a[nxt][i][0], a[nxt][i][1], a[nxt][i][2], a[nxt][i][3],
                          abn + (uint32_t)(i * 16 * 128) + col);
                #pragma unroll
                for (int q = 0; q < 4; q++) {
                    uint32_t r0, r1, r2, r3;
                    ldsm4(r0, r1, r2, r3, bbn + (uint32_t)(q * 16 * 128) + col);
                    b[nxt][2 * q][0] = r0; b[nxt][2 * q + 1][0] = r1;
                    b[nxt][2 * q][1] = r2; b[nxt][2 * q + 1][1] = r3;
                }
            }
            #pragma unroll
            for (int i = 0; i < 4; i++)
                #pragma unroll
                for (int j = 0; j < 8; j++)
                    mma_f16acc(acc[i][j], a[cur][i], b[cur][j]);
        }
    }

    // ---------------- epilogue: out = xsq + wsq - 2*acc ----------------
    // f16 acc layout: acc[i][j][0] = halves (row r, cols c2, c2+1); acc[i][j][1] = row r+8.
    int m0 = rt * BM + wm * 64;
    int n0 = ct * BN + wn * 64;
    int r = lane >> 2;
    int c2 = (lane & 3) * 2;

    #pragma unroll
    for (int i = 0; i < 4; i++) {
        int mA = m0 + i * 16 + r;
        float xs0 = __ldg(&g_xsq[mA]);
        float xs1 = __ldg(&g_xsq[mA + 8]);
        float* row0 = out + (size_t)mA * UDIM + n0;
        float* row1 = row0 + (size_t)8 * UDIM;
        #pragma unroll
        for (int j = 0; j < 8; j++) {
            float w0 = __ldg(&g_wsq[n0 + j * 8 + c2]);
            float w1 = __ldg(&g_wsq[n0 + j * 8 + c2 + 1]);
            float2 p0 = __half22float2(*reinterpret_cast<__half2*>(&acc[i][j][0]));
            float2 p1 = __half22float2(*reinterpret_cast<__half2*>(&acc[i][j][1]));
            float2 v0, v1;
            v0.x = xs0 + w0 - 2.0f * p0.x;
            v0.y = xs0 + w1 - 2.0f * p0.y;
            v1.x = xs1 + w0 - 2.0f * p1.x;
            v1.y = xs1 + w1 - 2.0f * p1.y;
            *reinterpret_cast<float2*>(row0 + j * 8 + c2) = v0;
            *reinterpret_cast<float2*>(row1 + j * 8 + c2) = v1;
        }
    }
}

// ------------------- launch -------------------
extern "C" void kernel_launch(void* const* d_in, const int* in_sizes, int n_in,
                              void* d_out, int out_size) {
    (void)in_sizes; (void)n_in; (void)out_size;
    const float* x = (const float*)d_in[0];   // [16384, 1024]
    const float* w = (const float*)d_in[1];   // [4096, 1024]
    float* out = (float*)d_out;               // [16384, 4096]

    cudaFuncSetAttribute(gemm_kernel, cudaFuncAttributeMaxDynamicSharedMemorySize, SMEM_TOTAL);

    convert_kernel<<<(NROWS + UDIM) / 8, 256>>>(x, w);
    gemm_kernel<<<(NROWS / BM) * (UDIM / BN), 128, SMEM_TOTAL>>>(out);
}